// round 1
// baseline (speedup 1.0000x reference)
#include <cuda_runtime.h>
#include <stdint.h>

// GCNConv: out = A @ (X @ W) + bias
//   X: [N, 64], W: [64, 64], edge_index: [2, E] (row0=dst, row1=src),
//   edge_weight: [E], bias: [64], out: [N, 64]
//
// Plan:
//   K1: support = X @ W          (smem-tiled, FFMA)  -> __device__ scratch
//   K2: out[i][j] = bias[j]      (init; d_out is poisoned)
//   K3: per-edge scatter: out[dst] += support[src] * w  via red.global.add.v4.f32

#define D_FEAT 64
#define N_MAX 100000

static __device__ __align__(16) float g_support[(size_t)N_MAX * D_FEAT];

// ---------------------------------------------------------------------------
// K1: support = X @ W.  Block = 256 threads, handles 64 rows of X.
// W (16KB) and the X tile (16KB) staged in shared memory.
// Thread t computes column c = t&63 for 16 rows (rbase = (t>>6)*16).
// ---------------------------------------------------------------------------
__global__ __launch_bounds__(256) void gemm_kernel(const float* __restrict__ x,
                                                   const float* __restrict__ w,
                                                   int N) {
    __shared__ float Ws[64 * 64];   // Ws[k*64 + c]
    __shared__ float Xs[64 * 64];   // Xs[r*64 + k]

    const int t = threadIdx.x;
    const int row0 = blockIdx.x * 64;

    // Load W (vectorized): 4096 floats = 1024 float4, 4 per thread.
    {
        const float4* w4 = reinterpret_cast<const float4*>(w);
        float4* ws4 = reinterpret_cast<float4*>(Ws);
        #pragma unroll
        for (int i = 0; i < 4; ++i) ws4[t + 256 * i] = w4[t + 256 * i];
    }
    // Load X tile (vectorized), zero-pad past N.
    {
        float4* xs4 = reinterpret_cast<float4*>(Xs);
        #pragma unroll
        for (int i = 0; i < 4; ++i) {
            int idx = t + 256 * i;            // float4 index within tile
            int r = idx >> 4;                 // 16 float4 per row
            int gr = row0 + r;
            if (gr < N) {
                xs4[idx] = reinterpret_cast<const float4*>(x)[(size_t)gr * 16 + (idx & 15)];
            } else {
                xs4[idx] = make_float4(0.f, 0.f, 0.f, 0.f);
            }
        }
    }
    __syncthreads();

    const int c = t & 63;
    const int rbase = (t >> 6) * 16;

    #pragma unroll 4
    for (int r = rbase; r < rbase + 16; ++r) {
        float acc = 0.f;
        #pragma unroll
        for (int k = 0; k < 64; ++k) {
            acc += Xs[r * 64 + k] * Ws[k * 64 + c];
        }
        int gr = row0 + r;
        if (gr < N) g_support[(size_t)gr * 64 + c] = acc;
    }
}

// ---------------------------------------------------------------------------
// K2: out[i][j] = bias[j]
// ---------------------------------------------------------------------------
__global__ __launch_bounds__(256) void init_out_kernel(float* __restrict__ out,
                                                       const float* __restrict__ bias,
                                                       int total) {
    __shared__ float4 b4[16];
    if (threadIdx.x < 16) {
        b4[threadIdx.x] = reinterpret_cast<const float4*>(bias)[threadIdx.x];
    }
    __syncthreads();
    int i = blockIdx.x * blockDim.x + threadIdx.x;   // float4 index
    if (i < total) {
        reinterpret_cast<float4*>(out)[i] = b4[i & 15];
    }
}

// ---------------------------------------------------------------------------
// K3: scatter. 16 threads per edge, each thread handles one float4 (4 cols).
// Vector reduction atomics: red.global.add.v4.f32 (sm_90+, no return value).
// ---------------------------------------------------------------------------
__global__ __launch_bounds__(256) void scatter_kernel(const int* __restrict__ edge_index,
                                                      const float* __restrict__ edge_weight,
                                                      float* __restrict__ out,
                                                      int E) {
    long long gid = (long long)blockIdx.x * blockDim.x + threadIdx.x;
    int e = (int)(gid >> 4);
    if (e >= E) return;
    int j = (int)(gid & 15);               // which float4 of the 64-wide row

    int dst = edge_index[e];               // row 0
    int src = edge_index[E + e];           // row 1
    float wgt = edge_weight[e];

    const float4 s = *reinterpret_cast<const float4*>(&g_support[(size_t)src * 64 + j * 4]);
    float* p = &out[(size_t)dst * 64 + j * 4];

    asm volatile("red.global.add.v4.f32 [%0], {%1, %2, %3, %4};"
                 :: "l"(p), "f"(s.x * wgt), "f"(s.y * wgt), "f"(s.z * wgt), "f"(s.w * wgt)
                 : "memory");
}

// ---------------------------------------------------------------------------
// launch
// ---------------------------------------------------------------------------
extern "C" void kernel_launch(void* const* d_in, const int* in_sizes, int n_in,
                              void* d_out, int out_size) {
    const float* x           = (const float*)d_in[0];   // [N, 64]
    const int*   edge_index  = (const int*)d_in[1];     // [2, E]
    const float* edge_weight = (const float*)d_in[2];   // [E]
    const float* weight      = (const float*)d_in[3];   // [64, 64]
    const float* bias        = (const float*)d_in[4];   // [64]
    float*       out         = (float*)d_out;

    const int N = in_sizes[0] / D_FEAT;
    const int E = in_sizes[2];

    // K1: support = X @ W
    {
        int blocks = (N + 63) / 64;
        gemm_kernel<<<blocks, 256>>>(x, weight, N);
    }
    // K2: out = bias (broadcast)
    {
        int total4 = N * (D_FEAT / 4);
        int blocks = (total4 + 255) / 256;
        init_out_kernel<<<blocks, 256>>>(out, bias, total4);
    }
    // K3: scatter-add over edges
    {
        long long threads = (long long)E * 16;
        int blocks = (int)((threads + 255) / 256);
        scatter_kernel<<<blocks, 256>>>(edge_index, edge_weight, out, E);
    }
}

// round 4
// speedup vs baseline: 1.0999x; 1.0999x over previous
#include <cuda_runtime.h>
#include <stdint.h>

// GCNConv: out = A @ (X @ W) + bias
//   X: [N, 64], W: [64, 64], edge_index: [2, E] (row0=dst, row1=src),
//   edge_weight: [E], bias: [64], out: [N, 64]
//
// Pipeline (no fp32 atomics; out written once, coalesced):
//   K1 gemm:      support = X @ W                          -> g_support
//   K2 zero:      g_count = 0
//   K3 hist:      g_count[dst]++                           (int atomics)
//   K4 scan1/2/3: exclusive prefix sum -> g_rowstart, g_pos
//   K5 place:     bucket edges by dst -> g_edges (src, weight) pairs
//   K6 aggregate: warp per dst: acc = sum support[src]*w; out = acc + bias

#define D_FEAT 64
#define N_MAX 131072
#define E_MAX 1700000

static __device__ __align__(16) float g_support[(size_t)100000 * D_FEAT];
static __device__ int  g_count[N_MAX];
static __device__ int  g_rowstart[N_MAX];
static __device__ int  g_pos[N_MAX];
static __device__ int  g_bsum[256];
static __device__ int2 g_edges[E_MAX];   // (.x = src, .y = bitcast weight)

// ---------------------------------------------------------------------------
// K1: support = X @ W.  Block = 256 threads, tile = 64 rows.
// k-outer, 16 register accumulators, float4 smem reads for X.
// ---------------------------------------------------------------------------
__global__ __launch_bounds__(256) void gemm_kernel(const float* __restrict__ x,
                                                   const float* __restrict__ w,
                                                   int N) {
    __shared__ float Ws[64 * 64];   // Ws[k*64 + c]
    __shared__ float Xs[64 * 64];   // Xs[r*64 + k]

    const int t = threadIdx.x;
    const int row0 = blockIdx.x * 64;

    {
        const float4* w4 = reinterpret_cast<const float4*>(w);
        float4* ws4 = reinterpret_cast<float4*>(Ws);
        #pragma unroll
        for (int i = 0; i < 4; ++i) ws4[t + 256 * i] = w4[t + 256 * i];
    }
    {
        float4* xs4 = reinterpret_cast<float4*>(Xs);
        #pragma unroll
        for (int i = 0; i < 4; ++i) {
            int idx = t + 256 * i;
            int r = idx >> 4;
            int gr = row0 + r;
            xs4[idx] = (gr < N)
                ? reinterpret_cast<const float4*>(x)[(size_t)gr * 16 + (idx & 15)]
                : make_float4(0.f, 0.f, 0.f, 0.f);
        }
    }
    __syncthreads();

    const int c = t & 63;
    const int rbase = (t >> 6) * 16;
    const float4* xs4 = reinterpret_cast<const float4*>(Xs);

    float acc[16];
    #pragma unroll
    for (int r = 0; r < 16; ++r) acc[r] = 0.f;

    #pragma unroll 4
    for (int k4 = 0; k4 < 16; ++k4) {
        float w0 = Ws[(4 * k4 + 0) * 64 + c];
        float w1 = Ws[(4 * k4 + 1) * 64 + c];
        float w2 = Ws[(4 * k4 + 2) * 64 + c];
        float w3 = Ws[(4 * k4 + 3) * 64 + c];
        #pragma unroll
        for (int r = 0; r < 16; ++r) {
            float4 xv = xs4[(rbase + r) * 16 + k4];
            acc[r] += xv.x * w0 + xv.y * w1 + xv.z * w2 + xv.w * w3;
        }
    }

    #pragma unroll
    for (int r = 0; r < 16; ++r) {
        int gr = row0 + rbase + r;
        if (gr < N) g_support[(size_t)gr * 64 + c] = acc[r];
    }
}

// ---------------------------------------------------------------------------
// K2: zero the histogram
// ---------------------------------------------------------------------------
__global__ __launch_bounds__(256) void zero_kernel(int N) {
    int i = blockIdx.x * blockDim.x + threadIdx.x;
    if (i < N) g_count[i] = 0;
}

// ---------------------------------------------------------------------------
// K3: histogram of dst
// ---------------------------------------------------------------------------
__global__ __launch_bounds__(256) void hist_kernel(const int* __restrict__ edge_index,
                                                   int E) {
    int e = blockIdx.x * blockDim.x + threadIdx.x;
    if (e < E) atomicAdd(&g_count[edge_index[e]], 1);
}

// ---------------------------------------------------------------------------
// K4a: per-chunk exclusive scan (chunk = 1024 elems, block = 256 threads x 4)
// ---------------------------------------------------------------------------
__global__ __launch_bounds__(256) void scan1_kernel(int N) {
    __shared__ int s[256];
    const int t = threadIdx.x;
    const int base = blockIdx.x * 1024 + t * 4;

    int v[4];
    int sum = 0;
    #pragma unroll
    for (int i = 0; i < 4; ++i) {
        v[i] = (base + i < N) ? g_count[base + i] : 0;
        sum += v[i];
    }
    s[t] = sum;
    __syncthreads();

    // inclusive Hillis-Steele scan of s
    #pragma unroll
    for (int off = 1; off < 256; off <<= 1) {
        int xval = (t >= off) ? s[t - off] : 0;
        __syncthreads();
        s[t] += xval;
        __syncthreads();
    }
    int excl = (t == 0) ? 0 : s[t - 1];
    if (t == 255) g_bsum[blockIdx.x] = s[255];

    int run = excl;
    #pragma unroll
    for (int i = 0; i < 4; ++i) {
        if (base + i < N) g_rowstart[base + i] = run;
        run += v[i];
    }
}

// ---------------------------------------------------------------------------
// K4b: scan block sums (single block, up to 256 chunks)
// ---------------------------------------------------------------------------
__global__ __launch_bounds__(256) void scan2_kernel(int nchunks) {
    __shared__ int s[256];
    const int t = threadIdx.x;
    s[t] = (t < nchunks) ? g_bsum[t] : 0;
    __syncthreads();
    #pragma unroll
    for (int off = 1; off < 256; off <<= 1) {
        int xval = (t >= off) ? s[t - off] : 0;
        __syncthreads();
        s[t] += xval;
        __syncthreads();
    }
    g_bsum[t] = (t == 0) ? 0 : s[t - 1];   // exclusive
}

// ---------------------------------------------------------------------------
// K4c: add chunk offsets; also init cursor g_pos
// ---------------------------------------------------------------------------
__global__ __launch_bounds__(256) void scan3_kernel(int N) {
    int i = blockIdx.x * blockDim.x + threadIdx.x;
    if (i < N) {
        int v = g_rowstart[i] + g_bsum[i >> 10];
        g_rowstart[i] = v;
        g_pos[i] = v;
    }
}

// ---------------------------------------------------------------------------
// K5: bucket edges by dst
// ---------------------------------------------------------------------------
__global__ __launch_bounds__(256) void place_kernel(const int* __restrict__ edge_index,
                                                    const float* __restrict__ edge_weight,
                                                    int E) {
    int e = blockIdx.x * blockDim.x + threadIdx.x;
    if (e >= E) return;
    int dst = edge_index[e];
    int src = edge_index[E + e];
    float wt = edge_weight[e];
    int p = atomicAdd(&g_pos[dst], 1);
    g_edges[p] = make_int2(src, __float_as_int(wt));
}

// ---------------------------------------------------------------------------
// K6: aggregation. One warp per dst row; lane owns 2 columns (float2).
// Edges loaded 32 at a time (one per lane), broadcast via shfl.
// ---------------------------------------------------------------------------
__global__ __launch_bounds__(256) void aggregate_kernel(const float* __restrict__ bias,
                                                        float* __restrict__ out,
                                                        int N) {
    const int warp = (blockIdx.x * blockDim.x + threadIdx.x) >> 5;
    const int lane = threadIdx.x & 31;
    if (warp >= N) return;

    const int start = g_rowstart[warp];
    const int deg   = g_count[warp];

    float2 acc = make_float2(0.f, 0.f);

    for (int base = 0; base < deg; base += 32) {
        int idx = base + lane;
        int2 e = (idx < deg) ? g_edges[start + idx] : make_int2(0, 0);
        int nv = min(32, deg - base);
        #pragma unroll 8
        for (int j = 0; j < nv; ++j) {
            int   src = __shfl_sync(0xFFFFFFFFu, e.x, j);
            float wt  = __int_as_float(__shfl_sync(0xFFFFFFFFu, e.y, j));
            float2 s = *reinterpret_cast<const float2*>(
                &g_support[(size_t)src * 64 + lane * 2]);
            acc.x += s.x * wt;
            acc.y += s.y * wt;
        }
    }

    float2 bv = *reinterpret_cast<const float2*>(&bias[lane * 2]);
    *reinterpret_cast<float2*>(&out[(size_t)warp * 64 + lane * 2]) =
        make_float2(acc.x + bv.x, acc.y + bv.y);
}

// ---------------------------------------------------------------------------
// launch
// ---------------------------------------------------------------------------
extern "C" void kernel_launch(void* const* d_in, const int* in_sizes, int n_in,
                              void* d_out, int out_size) {
    const float* x           = (const float*)d_in[0];   // [N, 64]
    const int*   edge_index  = (const int*)d_in[1];     // [2, E]
    const float* edge_weight = (const float*)d_in[2];   // [E]
    const float* weight      = (const float*)d_in[3];   // [64, 64]
    const float* bias        = (const float*)d_in[4];   // [64]
    float*       out         = (float*)d_out;

    const int N = in_sizes[0] / D_FEAT;
    const int E = in_sizes[2];
    const int nchunks = (N + 1023) / 1024;

    gemm_kernel<<<(N + 63) / 64, 256>>>(x, weight, N);

    zero_kernel<<<(N + 255) / 256, 256>>>(N);
    hist_kernel<<<(E + 255) / 256, 256>>>(edge_index, E);
    scan1_kernel<<<nchunks, 256>>>(N);
    scan2_kernel<<<1, 256>>>(nchunks);
    scan3_kernel<<<(N + 255) / 256, 256>>>(N);
    place_kernel<<<(E + 255) / 256, 256>>>(edge_index, edge_weight, E);

    const int warps_needed = N;                       // one warp per dst
    const int blocks = (warps_needed * 32 + 255) / 256;
    aggregate_kernel<<<blocks, 256>>>(bias, out, N);
}

// round 6
// speedup vs baseline: 1.2011x; 1.0920x over previous
#include <cuda_runtime.h>
#include <cuda_fp16.h>
#include <stdint.h>

// GCNConv: out = A @ (X @ W) + bias
//   X: [N, 64], W: [64, 64], edge_index: [2, E] (row0=dst, row1=src),
//   edge_weight: [E], bias: [64], out: [N, 64]
//
// Pipeline (no fp32 atomics; out written once, coalesced):
//   K1 gemm:      support = half(X @ W)                    -> g_support_h (fp16)
//   K2 zero:      g_count = 0
//   K3 hist:      g_count[dst]++                           (int atomics)
//   K4 scan1/2/3: exclusive prefix sum -> g_rowstart, g_pos
//   K5 place:     bucket edges by dst -> g_edges (src, weight) pairs
//   K6 aggregate: warp per dst: acc += half2(support[src]) * w; out = acc + bias
//
// fp16 support halves gather traffic (each gathered row = one 128B line);
// accumulation stays fp32 (quantization rel err ~2e-4 << 1e-3 tolerance).

#define D_FEAT 64
#define N_MAX 131072
#define E_MAX 1700000

static __device__ __align__(16) __half g_support_h[(size_t)100000 * D_FEAT];
static __device__ int  g_count[N_MAX];
static __device__ int  g_rowstart[N_MAX];
static __device__ int  g_pos[N_MAX];
static __device__ int  g_bsum[256];
static __device__ int2 g_edges[E_MAX];   // (.x = src, .y = bitcast fp32 weight)

// ---------------------------------------------------------------------------
// K1: support = X @ W, emitted as fp16.  Block = 256 threads, tile = 64 rows.
// Thread t owns 2 adjacent cols (c2 = (t&31)*2) x 8 rows (rbase = (t>>5)*8);
// stores 8 half2 (4B each), warp covers 128B contiguous per row.
// ---------------------------------------------------------------------------
__global__ __launch_bounds__(256) void gemm_kernel(const float* __restrict__ x,
                                                   const float* __restrict__ w,
                                                   int N) {
    __shared__ float Ws[64 * 64];   // Ws[k*64 + c]
    __shared__ float Xs[64 * 64];   // Xs[r*64 + k]

    const int t = threadIdx.x;
    const int row0 = blockIdx.x * 64;

    {
        const float4* w4 = reinterpret_cast<const float4*>(w);
        float4* ws4 = reinterpret_cast<float4*>(Ws);
        #pragma unroll
        for (int i = 0; i < 4; ++i) ws4[t + 256 * i] = w4[t + 256 * i];
    }
    {
        float4* xs4 = reinterpret_cast<float4*>(Xs);
        #pragma unroll
        for (int i = 0; i < 4; ++i) {
            int idx = t + 256 * i;
            int r = idx >> 4;
            int gr = row0 + r;
            xs4[idx] = (gr < N)
                ? reinterpret_cast<const float4*>(x)[(size_t)gr * 16 + (idx & 15)]
                : make_float4(0.f, 0.f, 0.f, 0.f);
        }
    }
    __syncthreads();

    const int c2    = (t & 31) * 2;      // column pair
    const int rbase = (t >> 5) * 8;      // 8 rows per thread
    const float4* xs4 = reinterpret_cast<const float4*>(Xs);

    float acc0[8], acc1[8];
    #pragma unroll
    for (int r = 0; r < 8; ++r) { acc0[r] = 0.f; acc1[r] = 0.f; }

    #pragma unroll 4
    for (int k4 = 0; k4 < 16; ++k4) {
        float wa0 = Ws[(4 * k4 + 0) * 64 + c2];
        float wb0 = Ws[(4 * k4 + 0) * 64 + c2 + 1];
        float wa1 = Ws[(4 * k4 + 1) * 64 + c2];
        float wb1 = Ws[(4 * k4 + 1) * 64 + c2 + 1];
        float wa2 = Ws[(4 * k4 + 2) * 64 + c2];
        float wb2 = Ws[(4 * k4 + 2) * 64 + c2 + 1];
        float wa3 = Ws[(4 * k4 + 3) * 64 + c2];
        float wb3 = Ws[(4 * k4 + 3) * 64 + c2 + 1];
        #pragma unroll
        for (int r = 0; r < 8; ++r) {
            float4 xv = xs4[(rbase + r) * 16 + k4];
            acc0[r] += xv.x * wa0 + xv.y * wa1 + xv.z * wa2 + xv.w * wa3;
            acc1[r] += xv.x * wb0 + xv.y * wb1 + xv.z * wb2 + xv.w * wb3;
        }
    }

    #pragma unroll
    for (int r = 0; r < 8; ++r) {
        int gr = row0 + rbase + r;
        if (gr < N) {
            *reinterpret_cast<__half2*>(&g_support_h[(size_t)gr * 64 + c2]) =
                __floats2half2_rn(acc0[r], acc1[r]);
        }
    }
}

// ---------------------------------------------------------------------------
// K2: zero the histogram
// ---------------------------------------------------------------------------
__global__ __launch_bounds__(256) void zero_kernel(int N) {
    int i = blockIdx.x * blockDim.x + threadIdx.x;
    if (i < N) g_count[i] = 0;
}

// ---------------------------------------------------------------------------
// K3: histogram of dst
// ---------------------------------------------------------------------------
__global__ __launch_bounds__(256) void hist_kernel(const int* __restrict__ edge_index,
                                                   int E) {
    int e = blockIdx.x * blockDim.x + threadIdx.x;
    if (e < E) atomicAdd(&g_count[edge_index[e]], 1);
}

// ---------------------------------------------------------------------------
// K4a: per-chunk exclusive scan (chunk = 1024, block = 256 thr x 4 elems).
// Warp-shuffle scan: 2 syncthreads total.
// ---------------------------------------------------------------------------
__global__ __launch_bounds__(256) void scan1_kernel(int N) {
    __shared__ int wsum[8];
    const int t    = threadIdx.x;
    const int lane = t & 31;
    const int wid  = t >> 5;
    const int base = blockIdx.x * 1024 + t * 4;

    int v[4];
    int sum = 0;
    #pragma unroll
    for (int i = 0; i < 4; ++i) {
        v[i] = (base + i < N) ? g_count[base + i] : 0;
        sum += v[i];
    }

    // inclusive warp scan of per-thread sums
    int incl = sum;
    #pragma unroll
    for (int off = 1; off < 32; off <<= 1) {
        int up = __shfl_up_sync(0xFFFFFFFFu, incl, off);
        if (lane >= off) incl += up;
    }
    if (lane == 31) wsum[wid] = incl;
    __syncthreads();

    if (wid == 0) {
        int wv = (lane < 8) ? wsum[lane] : 0;
        int wi = wv;
        #pragma unroll
        for (int off = 1; off < 8; off <<= 1) {
            int up = __shfl_up_sync(0xFFFFFFFFu, wi, off);
            if (lane >= off) wi += up;
        }
        if (lane < 8) wsum[lane] = wi - wv;      // exclusive warp offsets
        if (lane == 7 && blockIdx.x < 256) g_bsum[blockIdx.x] = wi;  // chunk total
    }
    __syncthreads();

    int run = wsum[wid] + incl - sum;            // exclusive prefix for this thread
    #pragma unroll
    for (int i = 0; i < 4; ++i) {
        if (base + i < N) g_rowstart[base + i] = run;
        run += v[i];
    }
}

// ---------------------------------------------------------------------------
// K4b: scan block sums (single block, up to 256 chunks)
// ---------------------------------------------------------------------------
__global__ __launch_bounds__(256) void scan2_kernel(int nchunks) {
    __shared__ int s[256];
    const int t = threadIdx.x;
    s[t] = (t < nchunks) ? g_bsum[t] : 0;
    __syncthreads();
    #pragma unroll
    for (int off = 1; off < 256; off <<= 1) {
        int xval = (t >= off) ? s[t - off] : 0;
        __syncthreads();
        s[t] += xval;
        __syncthreads();
    }
    g_bsum[t] = (t == 0) ? 0 : s[t - 1];   // exclusive
}

// ---------------------------------------------------------------------------
// K4c: add chunk offsets; also init cursor g_pos
// ---------------------------------------------------------------------------
__global__ __launch_bounds__(256) void scan3_kernel(int N) {
    int i = blockIdx.x * blockDim.x + threadIdx.x;
    if (i < N) {
        int v = g_rowstart[i] + g_bsum[i >> 10];
        g_rowstart[i] = v;
        g_pos[i] = v;
    }
}

// ---------------------------------------------------------------------------
// K5: bucket edges by dst
// ---------------------------------------------------------------------------
__global__ __launch_bounds__(256) void place_kernel(const int* __restrict__ edge_index,
                                                    const float* __restrict__ edge_weight,
                                                    int E) {
    int e = blockIdx.x * blockDim.x + threadIdx.x;
    if (e >= E) return;
    int dst = edge_index[e];
    int src = edge_index[E + e];
    float wt = edge_weight[e];
    int p = atomicAdd(&g_pos[dst], 1);
    g_edges[p] = make_int2(src, __float_as_int(wt));
}

// ---------------------------------------------------------------------------
// K6: aggregation. One warp per dst row; lane owns 2 columns.
// Edge records read warp-uniform (broadcast LDG.64, L1-hit 15/16 times);
// support gathered as half2 -> one 128B line per edge.
// ---------------------------------------------------------------------------
__global__ __launch_bounds__(256) void aggregate_kernel(const float* __restrict__ bias,
                                                        float* __restrict__ out,
                                                        int N) {
    const int warp = (blockIdx.x * blockDim.x + threadIdx.x) >> 5;
    const int lane = threadIdx.x & 31;
    if (warp >= N) return;

    const int start = g_rowstart[warp];
    const int end   = start + g_count[warp];

    float2 acc = make_float2(0.f, 0.f);

    #pragma unroll 4
    for (int j = start; j < end; ++j) {
        int2 e = __ldg(&g_edges[j]);                 // warp-uniform broadcast
        float wt = __int_as_float(e.y);
        __half2 h = *reinterpret_cast<const __half2*>(
            &g_support_h[(size_t)e.x * 64 + lane * 2]);
        float2 s = __half22float2(h);
        acc.x = fmaf(s.x, wt, acc.x);
        acc.y = fmaf(s.y, wt, acc.y);
    }

    float2 bv = *reinterpret_cast<const float2*>(&bias[lane * 2]);
    *reinterpret_cast<float2*>(&out[(size_t)warp * 64 + lane * 2]) =
        make_float2(acc.x + bv.x, acc.y + bv.y);
}

// ---------------------------------------------------------------------------
// launch
// ---------------------------------------------------------------------------
extern "C" void kernel_launch(void* const* d_in, const int* in_sizes, int n_in,
                              void* d_out, int out_size) {
    const float* x           = (const float*)d_in[0];   // [N, 64]
    const int*   edge_index  = (const int*)d_in[1];     // [2, E]
    const float* edge_weight = (const float*)d_in[2];   // [E]
    const float* weight      = (const float*)d_in[3];   // [64, 64]
    const float* bias        = (const float*)d_in[4];   // [64]
    float*       out         = (float*)d_out;

    const int N = in_sizes[0] / D_FEAT;
    const int E = in_sizes[2];
    const int nchunks = (N + 1023) / 1024;

    gemm_kernel<<<(N + 63) / 64, 256>>>(x, weight, N);

    zero_kernel<<<(N + 255) / 256, 256>>>(N);
    hist_kernel<<<(E + 255) / 256, 256>>>(edge_index, E);
    scan1_kernel<<<nchunks, 256>>>(N);
    scan2_kernel<<<1, 256>>>(nchunks);
    scan3_kernel<<<(N + 255) / 256, 256>>>(N);
    place_kernel<<<(E + 255) / 256, 256>>>(edge_index, edge_weight, E);

    const int blocks = (N * 32 + 255) / 256;            // one warp per dst row
    aggregate_kernel<<<blocks, 256>>>(bias, out, N);
}